// round 13
// baseline (speedup 1.0000x reference)
#include <cuda_runtime.h>
#include <cuda_bf16.h>
#include <cstdint>

#define BATCH 8192
#define DIM   2048
#define EPSV  1e-8f
#define MARGINV 0.2f

static constexpr int THREADS = 256;
static constexpr int ROW_F4  = DIM / 4;   // 512
static constexpr int HALF    = BATCH / 2; // 4096

__device__ __forceinline__ float dot4(float4 a, float4 b) {
    return a.x * b.x + a.y * b.y + a.z * b.z + a.w * b.w;
}

// Compute the 11 reduced dot-products for one row into acc[0..10].
// Phased loads: 8 live float4 in phase 1, 4 more (reusing dead regs) in phase 2.
__device__ __forceinline__ void row_accs(const float4* __restrict__ img,
                                         const float4* __restrict__ txt,
                                         const int2* __restrict__ cand_img,
                                         const int2* __restrict__ cand_txt,
                                         int row, int t, float* acc) {
    const int2 va = cand_img[row];
    const int2 vb = cand_txt[row];
    const int a0 = va.x & (BATCH - 1), a1 = va.y & (BATCH - 1);
    const int b0 = vb.x & (BATCH - 1), b1 = vb.y & (BATCH - 1);

    const float4* ir  = img + (size_t)row * ROW_F4;
    const float4* tr  = txt + (size_t)row * ROW_F4;
    const float4* gA0 = img + (size_t)a0 * ROW_F4;
    const float4* gA1 = img + (size_t)a1 * ROW_F4;

    const float4 iv0 = ir[t],  iv1 = ir[t + THREADS];
    const float4 tv0 = tr[t],  tv1 = tr[t + THREADS];
    const float4 A00 = gA0[t], A01 = gA0[t + THREADS];
    const float4 A10 = gA1[t], A11 = gA1[t + THREADS];

    acc[0] = dot4(iv0, iv0) + dot4(iv1, iv1);   // ||img||^2
    acc[1] = dot4(tv0, tv0) + dot4(tv1, tv1);   // ||text||^2
    acc[2] = dot4(iv0, tv0) + dot4(iv1, tv1);   // img.text
    acc[3] = dot4(tv0, A00) + dot4(tv1, A01);   // text . img[a0]
    acc[4] = dot4(A00, A00) + dot4(A01, A01);   // ||img[a0]||^2
    acc[5] = dot4(tv0, A10) + dot4(tv1, A11);
    acc[6] = dot4(A10, A10) + dot4(A11, A11);

    const float4* gB0 = txt + (size_t)b0 * ROW_F4;
    const float4* gB1 = txt + (size_t)b1 * ROW_F4;
    const float4 B00 = gB0[t], B01 = gB0[t + THREADS];
    const float4 B10 = gB1[t], B11 = gB1[t + THREADS];

    acc[7]  = dot4(iv0, B00) + dot4(iv1, B01);  // img . text[b0]
    acc[8]  = dot4(B00, B00) + dot4(B01, B01);
    acc[9]  = dot4(iv0, B10) + dot4(iv1, B11);
    acc[10] = dot4(B10, B10) + dot4(B11, B11);
}

// From 11 reduced sums, compute and emit outputs for `row`.
__device__ __forceinline__ void epilogue(const float* rr, int row,
                                         float* __restrict__ out) {
    const float n_i = sqrtf(rr[0]);
    const float n_t = sqrtf(rr[1]);
    const float prod = n_i * n_t;
    const float pos_dist = 1.0f - rr[2] / fmaxf(prod, EPSV);
    const float cosv = rr[2] / prod;

    const float dA0 = 1.0f - rr[3] / fmaxf(n_t * sqrtf(rr[4]), EPSV);
    const float dA1 = 1.0f - rr[5] / fmaxf(n_t * sqrtf(rr[6]), EPSV);
    const float t2i_neg = (dA1 <= dA0) ? dA1 : dA0;

    const float dB0 = 1.0f - rr[7] / fmaxf(n_i * sqrtf(rr[8]), EPSV);
    const float dB1 = 1.0f - rr[9] / fmaxf(n_i * sqrtf(rr[10]), EPSV);
    const float i2t_neg = (dB1 <= dB0) ? dB1 : dB0;

    const float i2t_loss = fmaxf(pos_dist - i2t_neg + MARGINV, 0.0f);
    const float t2i_loss = fmaxf(pos_dist - t2i_neg + MARGINV, 0.0f);

    out[1 + row]         = cosv;   // i2t_cosine
    out[1 + BATCH + row] = cosv;   // t2i_cosine (same symmetric formula)
    atomicAdd(&out[0], (i2t_loss + t2i_loss) * (1.0f / (float)BATCH));
}

__global__ __launch_bounds__(THREADS)
void contrastive_main(const float4* __restrict__ img,
                      const float4* __restrict__ txt,
                      const int2* __restrict__ cand_img,
                      const int2* __restrict__ cand_txt,
                      float* __restrict__ out) {
    const int t    = threadIdx.x;
    const int row0 = blockIdx.x;
    const int row1 = blockIdx.x + HALF;

    // 22 accumulators across both rows; loads of row1 overlap row0's FFMAs,
    // and there is only ONE reduction + sync + epilogue for both rows.
    float acc[22];
    row_accs(img, txt, cand_img, cand_txt, row0, t, acc);
    row_accs(img, txt, cand_img, cand_txt, row1, t, acc + 11);

    #pragma unroll
    for (int k = 0; k < 22; k++) {
        float v = acc[k];
        #pragma unroll
        for (int off = 16; off > 0; off >>= 1)
            v += __shfl_xor_sync(0xFFFFFFFFu, v, off);
        acc[k] = v;
    }

    __shared__ float s[THREADS / 32][22];
    const int lane = t & 31, warp = t >> 5;
    if (lane == 0) {
        #pragma unroll
        for (int k = 0; k < 22; k++) s[warp][k] = acc[k];
    }
    __syncthreads();

    if (warp == 0) {
        // lane k (k<22) owns accumulator k: parallel cross-warp sum
        float r = 0.f;
        if (lane < 22) {
            #pragma unroll
            for (int w = 0; w < THREADS / 32; w++) r += s[w][lane];
        }
        float rr[22];
        #pragma unroll
        for (int k = 0; k < 22; k++)
            rr[k] = __shfl_sync(0xFFFFFFFFu, r, k);

        if (lane == 0) {
            epilogue(rr,      row0, out);
            epilogue(rr + 11, row1, out);
        }
    }
}

extern "C" void kernel_launch(void* const* d_in, const int* in_sizes, int n_in,
                              void* d_out, int out_size) {
    const float4* img = (const float4*)d_in[0];
    const float4* txt = (const float4*)d_in[1];
    // d_in[2] = labels (unused), d_in[3] = locations (unused)
    const int2* cand_img = (const int2*)d_in[4];
    const int2* cand_txt = (const int2*)d_in[5];
    float* out = (float*)d_out;

    // zero the loss accumulator (4 bytes) — graph-capturable memset node,
    // resets out[0] on every replay so the atomic sum starts clean
    cudaMemsetAsync(out, 0, sizeof(float));

    contrastive_main<<<HALF, THREADS>>>(img, txt, cand_img, cand_txt, out);
}

// round 14
// speedup vs baseline: 1.0428x; 1.0428x over previous
#include <cuda_runtime.h>
#include <cuda_bf16.h>
#include <cstdint>

#define BATCH 8192
#define DIM   2048
#define EPSV  1e-8f
#define MARGINV 0.2f

static constexpr int THREADS = 256;
static constexpr int ROW_F4  = DIM / 4;   // 512

__device__ __forceinline__ float dot4(float4 a, float4 b) {
    return a.x * b.x + a.y * b.y + a.z * b.z + a.w * b.w;
}

__device__ __forceinline__ void cp16(uint32_t dst, const float4* src) {
    asm volatile("cp.async.cg.shared.global [%0], [%1], 16;" :: "r"(dst), "l"(src));
}

__global__ __launch_bounds__(THREADS, 7)
void contrastive_main(const float4* __restrict__ img,
                      const float4* __restrict__ txt,
                      const int2* __restrict__ cand_img,
                      const int2* __restrict__ cand_txt,
                      float* __restrict__ out) {
    // B-row staging: [0..511] = txt[b0], [512..1023] = txt[b1]  (16 KB)
    __shared__ float4 sbuf[2 * ROW_F4];
    __shared__ float s[THREADS / 32][11];

    const int row = blockIdx.x;
    const int t   = threadIdx.x;

    // cand arrays are int32 (JAX x64-disabled downcast; proven in R1->R2)
    const int2 va = cand_img[row];
    const int2 vb = cand_txt[row];
    const int a0 = va.x & (BATCH - 1), a1 = va.y & (BATCH - 1);
    const int b0 = vb.x & (BATCH - 1), b1 = vb.y & (BATCH - 1);

    // Phase-2 rows go through cp.async NOW (no destination registers) so all
    // 12 row-loads are in flight before any math. Each thread stages exactly
    // the words it will read back -> per-thread wait, no __syncthreads needed.
    {
        const float4* gB0 = txt + (size_t)b0 * ROW_F4;
        const float4* gB1 = txt + (size_t)b1 * ROW_F4;
        const uint32_t sb = (uint32_t)__cvta_generic_to_shared(sbuf);
        cp16(sb + (uint32_t)(t)                    * 16, gB0 + t);
        cp16(sb + (uint32_t)(t + THREADS)          * 16, gB0 + t + THREADS);
        cp16(sb + (uint32_t)(ROW_F4 + t)           * 16, gB1 + t);
        cp16(sb + (uint32_t)(ROW_F4 + t + THREADS) * 16, gB1 + t + THREADS);
        asm volatile("cp.async.commit_group;");
    }

    const float4* ir = img + (size_t)row * ROW_F4;
    const float4* tr = txt + (size_t)row * ROW_F4;

    float acc[11];

    // ---- Phase 1: anchors + img-candidate gathers (8 loads live) ----
    float4 iv0, iv1;
    {
        const float4* gA0 = img + (size_t)a0 * ROW_F4;
        const float4* gA1 = img + (size_t)a1 * ROW_F4;
        iv0 = ir[t];  iv1 = ir[t + THREADS];
        const float4 tv0 = tr[t],  tv1 = tr[t + THREADS];
        const float4 A00 = gA0[t], A01 = gA0[t + THREADS];
        const float4 A10 = gA1[t], A11 = gA1[t + THREADS];

        acc[0] = dot4(iv0, iv0) + dot4(iv1, iv1);   // ||img||^2
        acc[1] = dot4(tv0, tv0) + dot4(tv1, tv1);   // ||text||^2
        acc[2] = dot4(iv0, tv0) + dot4(iv1, tv1);   // img.text
        acc[3] = dot4(tv0, A00) + dot4(tv1, A01);   // text . img[a0]
        acc[4] = dot4(A00, A00) + dot4(A01, A01);   // ||img[a0]||^2
        acc[5] = dot4(tv0, A10) + dot4(tv1, A11);
        acc[6] = dot4(A10, A10) + dot4(A11, A11);
    }

    // ---- Phase 2: staged text-candidate rows from smem ----
    {
        asm volatile("cp.async.wait_group 0;");
        const float4 B00 = sbuf[t],          B01 = sbuf[t + THREADS];
        const float4 B10 = sbuf[ROW_F4 + t], B11 = sbuf[ROW_F4 + t + THREADS];

        acc[7]  = dot4(iv0, B00) + dot4(iv1, B01);  // img . text[b0]
        acc[8]  = dot4(B00, B00) + dot4(B01, B01);
        acc[9]  = dot4(iv0, B10) + dot4(iv1, B11);
        acc[10] = dot4(B10, B10) + dot4(B11, B11);
    }

    #pragma unroll
    for (int k = 0; k < 11; k++) {
        float v = acc[k];
        #pragma unroll
        for (int off = 16; off > 0; off >>= 1)
            v += __shfl_xor_sync(0xFFFFFFFFu, v, off);
        acc[k] = v;
    }

    const int lane = t & 31, warp = t >> 5;
    if (lane == 0) {
        #pragma unroll
        for (int k = 0; k < 11; k++) s[warp][k] = acc[k];
    }
    __syncthreads();

    if (warp == 0) {
        // lane k (k<11) owns accumulator k: parallel cross-warp sum
        float r = 0.f;
        if (lane < 11) {
            #pragma unroll
            for (int w = 0; w < THREADS / 32; w++) r += s[w][lane];
        }
        float rr[11];
        #pragma unroll
        for (int k = 0; k < 11; k++)
            rr[k] = __shfl_sync(0xFFFFFFFFu, r, k);

        if (lane == 0) {
            const float n_i = sqrtf(rr[0]);
            const float n_t = sqrtf(rr[1]);
            const float prod = n_i * n_t;
            const float pos_dist = 1.0f - rr[2] / fmaxf(prod, EPSV);
            const float cosv = rr[2] / prod;

            const float dA0 = 1.0f - rr[3] / fmaxf(n_t * sqrtf(rr[4]), EPSV);
            const float dA1 = 1.0f - rr[5] / fmaxf(n_t * sqrtf(rr[6]), EPSV);
            const float t2i_neg = (dA1 <= dA0) ? dA1 : dA0;

            const float dB0 = 1.0f - rr[7] / fmaxf(n_i * sqrtf(rr[8]), EPSV);
            const float dB1 = 1.0f - rr[9] / fmaxf(n_i * sqrtf(rr[10]), EPSV);
            const float i2t_neg = (dB1 <= dB0) ? dB1 : dB0;

            const float i2t_loss = fmaxf(pos_dist - i2t_neg + MARGINV, 0.0f);
            const float t2i_loss = fmaxf(pos_dist - t2i_neg + MARGINV, 0.0f);

            out[1 + row]         = cosv;   // i2t_cosine
            out[1 + BATCH + row] = cosv;   // t2i_cosine (same symmetric formula)
            atomicAdd(&out[0], (i2t_loss + t2i_loss) * (1.0f / (float)BATCH));
        }
    }
}

extern "C" void kernel_launch(void* const* d_in, const int* in_sizes, int n_in,
                              void* d_out, int out_size) {
    const float4* img = (const float4*)d_in[0];
    const float4* txt = (const float4*)d_in[1];
    // d_in[2] = labels (unused), d_in[3] = locations (unused)
    const int2* cand_img = (const int2*)d_in[4];
    const int2* cand_txt = (const int2*)d_in[5];
    float* out = (float*)d_out;

    // zero the loss accumulator (4 bytes) — graph-capturable memset node,
    // resets out[0] on every replay so the atomic sum starts clean
    cudaMemsetAsync(out, 0, sizeof(float));

    contrastive_main<<<BATCH, THREADS>>>(img, txt, cand_img, cand_txt, out);
}

// round 16
// speedup vs baseline: 1.1261x; 1.0799x over previous
#include <cuda_runtime.h>
#include <cuda_bf16.h>
#include <cstdint>

#define BATCH 8192
#define DIM   2048
#define EPSV  1e-8f
#define MARGINV 0.2f

static constexpr int THREADS = 256;
static constexpr int ROW_F4  = DIM / 4;   // 512

__device__ __forceinline__ float dot4(float4 a, float4 b) {
    return a.x * b.x + a.y * b.y + a.z * b.z + a.w * b.w;
}

__global__ __launch_bounds__(THREADS, 7)   // 32 regs -> 7 blocks/SM (proven R10)
void contrastive_main(const float4* __restrict__ img,
                      const float4* __restrict__ txt,
                      const int2* __restrict__ cand_img,
                      const int2* __restrict__ cand_txt,
                      float* __restrict__ out) {
    const int row = blockIdx.x;
    const int t   = threadIdx.x;

    // cand arrays are int32 (JAX x64-disabled downcast; proven in R1->R2)
    const int2 va = cand_img[row];
    const int2 vb = cand_txt[row];
    const int a0 = va.x & (BATCH - 1), a1 = va.y & (BATCH - 1);
    const int b0 = vb.x & (BATCH - 1), b1 = vb.y & (BATCH - 1);

    const float4* ir = img + (size_t)row * ROW_F4;
    const float4* tr = txt + (size_t)row * ROW_F4;

    float acc[11];

    // L2 policy: anchors are read-once streams -> __ldcs (evict-first, don't
    // displace reusable lines). Gathers have ~2x expected reuse across blocks
    // -> __ldcg (normal L2 allocate). Goal: keep the gather working set
    // resident in the 126MB L2 and cut the ~82MB of capacity-miss DRAM traffic.
    // ---- Phase 1: anchors + img-candidate gathers (8 loads live) ----
    {
        const float4* gA0 = img + (size_t)a0 * ROW_F4;
        const float4* gA1 = img + (size_t)a1 * ROW_F4;
        const float4 iv0 = __ldcs(ir + t),  iv1 = __ldcs(ir + t + THREADS);
        const float4 tv0 = __ldcs(tr + t),  tv1 = __ldcs(tr + t + THREADS);
        const float4 A00 = __ldcg(gA0 + t), A01 = __ldcg(gA0 + t + THREADS);
        const float4 A10 = __ldcg(gA1 + t), A11 = __ldcg(gA1 + t + THREADS);

        acc[0] = dot4(iv0, iv0) + dot4(iv1, iv1);   // ||img||^2
        acc[1] = dot4(tv0, tv0) + dot4(tv1, tv1);   // ||text||^2
        acc[2] = dot4(iv0, tv0) + dot4(iv1, tv1);   // img.text
        acc[3] = dot4(tv0, A00) + dot4(tv1, A01);   // text . img[a0]
        acc[4] = dot4(A00, A00) + dot4(A01, A01);   // ||img[a0]||^2
        acc[5] = dot4(tv0, A10) + dot4(tv1, A11);
        acc[6] = dot4(A10, A10) + dot4(A11, A11);

        // ---- Phase 2: text-candidate gathers (A regs dead, reuse) ----
        const float4* gB0 = txt + (size_t)b0 * ROW_F4;
        const float4* gB1 = txt + (size_t)b1 * ROW_F4;
        const float4 B00 = __ldcg(gB0 + t), B01 = __ldcg(gB0 + t + THREADS);
        const float4 B10 = __ldcg(gB1 + t), B11 = __ldcg(gB1 + t + THREADS);

        acc[7]  = dot4(iv0, B00) + dot4(iv1, B01);  // img . text[b0]
        acc[8]  = dot4(B00, B00) + dot4(B01, B01);
        acc[9]  = dot4(iv0, B10) + dot4(iv1, B11);
        acc[10] = dot4(B10, B10) + dot4(B11, B11);
    }

    #pragma unroll
    for (int k = 0; k < 11; k++) {
        float v = acc[k];
        #pragma unroll
        for (int off = 16; off > 0; off >>= 1)
            v += __shfl_xor_sync(0xFFFFFFFFu, v, off);
        acc[k] = v;
    }

    __shared__ float s[THREADS / 32][11];
    const int lane = t & 31, warp = t >> 5;
    if (lane == 0) {
        #pragma unroll
        for (int k = 0; k < 11; k++) s[warp][k] = acc[k];
    }
    __syncthreads();

    if (warp == 0) {
        // lane k (k<11) owns accumulator k: parallel cross-warp sum
        float r = 0.f;
        if (lane < 11) {
            #pragma unroll
            for (int w = 0; w < THREADS / 32; w++) r += s[w][lane];
        }
        float rr[11];
        #pragma unroll
        for (int k = 0; k < 11; k++)
            rr[k] = __shfl_sync(0xFFFFFFFFu, r, k);

        if (lane == 0) {
            const float n_i = sqrtf(rr[0]);
            const float n_t = sqrtf(rr[1]);
            const float prod = n_i * n_t;
            const float pos_dist = 1.0f - rr[2] / fmaxf(prod, EPSV);
            const float cosv = rr[2] / prod;

            const float dA0 = 1.0f - rr[3] / fmaxf(n_t * sqrtf(rr[4]), EPSV);
            const float dA1 = 1.0f - rr[5] / fmaxf(n_t * sqrtf(rr[6]), EPSV);
            const float t2i_neg = (dA1 <= dA0) ? dA1 : dA0;

            const float dB0 = 1.0f - rr[7] / fmaxf(n_i * sqrtf(rr[8]), EPSV);
            const float dB1 = 1.0f - rr[9] / fmaxf(n_i * sqrtf(rr[10]), EPSV);
            const float i2t_neg = (dB1 <= dB0) ? dB1 : dB0;

            const float i2t_loss = fmaxf(pos_dist - i2t_neg + MARGINV, 0.0f);
            const float t2i_loss = fmaxf(pos_dist - t2i_neg + MARGINV, 0.0f);

            out[1 + row]         = cosv;   // i2t_cosine
            out[1 + BATCH + row] = cosv;   // t2i_cosine (same symmetric formula)

            // fire-and-forget reduction straight into out[0] (zeroed by the
            // preceding 4-byte memset node each replay)
            atomicAdd(&out[0], (i2t_loss + t2i_loss) * (1.0f / (float)BATCH));
        }
    }
}

extern "C" void kernel_launch(void* const* d_in, const int* in_sizes, int n_in,
                              void* d_out, int out_size) {
    const float4* img = (const float4*)d_in[0];
    const float4* txt = (const float4*)d_in[1];
    // d_in[2] = labels (unused), d_in[3] = locations (unused)
    const int2* cand_img = (const int2*)d_in[4];
    const int2* cand_txt = (const int2*)d_in[5];
    float* out = (float*)d_out;

    // zero the loss accumulator (4 bytes) — graph-capturable memset node,
    // resets out[0] on every replay so the atomic sum starts clean
    cudaMemsetAsync(out, 0, sizeof(float));

    contrastive_main<<<BATCH, THREADS>>>(img, txt, cand_img, cand_txt, out);
}